// round 13
// baseline (speedup 1.0000x reference)
#include <cuda_runtime.h>
#include <cuda_fp16.h>
#include <math.h>

#define N_NODES 200000
#define N_USERS 100000
#define DIM 64
#define E_MAX   1200000
#define NODES_PER_SCAN_BLK 1024
#define NUM_SCAN_BLOCKS ((N_NODES + NODES_PER_SCAN_BLK - 1) / NODES_PER_SCAN_BLK)  // 196
#define GEMM_ROWS 128

// ---- device scratch (static globals; zero-initialized at module load) ----
__device__ int   g_cnt[N_NODES];        // zeroed by scan3 of the SAME launch after use
__device__ int   g_off[N_NODES];
__device__ int   g_cur[N_NODES];
__device__ float g_dinv[N_NODES];
__device__ float g_a[N_NODES];          // a = A_norm . 1
__device__ int   g_bsum[NUM_SCAN_BLOCKS];
__device__ int   g_src[E_MAX];
__device__ __half g_Wch[64 * 64];       // (W1@W2)^T in fp16, layout [n][k]
__device__ float  g_bv[64];             // b1 @ W2
__device__ __half g_zh[(size_t)N_NODES * DIM];  // zs = dinv*(x@Wc), fp16
__device__ __half g_hh[(size_t)N_NODES * DIM];  // u1, fp16

// per-block dtype detection: int64 edge entries have zero hi-words.
// requires blockDim.x == 256 and E >= 256.
__device__ __forceinline__ int detect_is64(const unsigned int* raw) {
    __shared__ int s_hi;
    if (threadIdx.x == 0) s_hi = 0;
    __syncthreads();
    if (raw[threadIdx.x * 2 + 1] != 0u) s_hi = 1;   // benign race
    __syncthreads();
    return s_hi == 0;
}

__device__ __forceinline__ int load_idx(const void* ei, size_t pos, int is64) {
    if (is64) return (int)((const long long*)ei)[pos];
    return ((const int*)ei)[pos];
}
__device__ __forceinline__ void load_idx2(const void* ei, size_t pos, int is64,
                                          int& a, int& b) {
    if (is64) {
        longlong2 v = *(const longlong2*)((const long long*)ei + pos);
        a = (int)v.x; b = (int)v.y;
    } else {
        int2 v = *(const int2*)((const int*)ei + pos);
        a = v.x; b = v.y;
    }
}

// accumulate 8 halves (uint4) into 8 fp32 accumulators
__device__ __forceinline__ void h8_add(float* acc, uint4 v) {
    float2 f;
    f = __half22float2(*(__half2*)&v.x); acc[0] += f.x; acc[1] += f.y;
    f = __half22float2(*(__half2*)&v.y); acc[2] += f.x; acc[3] += f.y;
    f = __half22float2(*(__half2*)&v.z); acc[4] += f.x; acc[5] += f.y;
    f = __half22float2(*(__half2*)&v.w); acc[6] += f.x; acc[7] += f.y;
}

// ------------------------------------------------------------------
// in-degree histogram over col = edge_index[1]; 2 edges per thread
// (g_cnt arrives zeroed: module-load init on call 1, scan3 self-clean after)
__global__ __launch_bounds__(256) void k_hist(const void* __restrict__ ei, int E) {
    int is64 = detect_is64((const unsigned int*)ei);
    int e = (blockIdx.x * blockDim.x + threadIdx.x) * 2;
    if (e + 1 < E) {
        int c0, c1;
        load_idx2(ei, (size_t)E + e, is64, c0, c1);
        if ((unsigned)c0 < (unsigned)N_NODES) atomicAdd(&g_cnt[c0], 1);
        if ((unsigned)c1 < (unsigned)N_NODES) atomicAdd(&g_cnt[c1], 1);
    } else if (e < E) {
        int c = load_idx(ei, (size_t)E + e, is64);
        if ((unsigned)c < (unsigned)N_NODES) atomicAdd(&g_cnt[c], 1);
    }
}

// ---- scan stage 1: per-1024-node block local scan + block totals ----
__global__ __launch_bounds__(256) void k_scan1() {
    __shared__ int sbuf[2][256];
    int t = threadIdx.x;
    int base = blockIdx.x * NODES_PER_SCAN_BLK + t * 4;
    int v[4]; int sum = 0;
#pragma unroll
    for (int q = 0; q < 4; ++q) {
        v[q] = (base + q < N_NODES) ? g_cnt[base + q] : 0;
        sum += v[q];
    }
    sbuf[0][t] = sum;
    __syncthreads();
    int cur = 0;
#pragma unroll
    for (int d = 1; d < 256; d <<= 1) {
        int x = sbuf[cur][t];
        if (t >= d) x += sbuf[cur][t - d];
        sbuf[1 - cur][t] = x;
        cur ^= 1;
        __syncthreads();
    }
    int incl = sbuf[cur][t];
    int excl = incl - sum;
#pragma unroll
    for (int q = 0; q < 4; ++q) {
        if (base + q < N_NODES) g_off[base + q] = excl;
        excl += v[q];
    }
    if (t == 255) g_bsum[blockIdx.x] = incl;
}

// ---- scan stage 2 (fused): re-scan 196 partials per block, finalize
//      offsets/cursors/dinv, then self-clean g_cnt for the next launch ----
__global__ __launch_bounds__(256) void k_scan3() {
    __shared__ int sbuf[2][256];
    __shared__ int pre[NUM_SCAN_BLOCKS];
    int t = threadIdx.x;
    int val = (t < NUM_SCAN_BLOCKS) ? g_bsum[t] : 0;
    sbuf[0][t] = val;
    __syncthreads();
    int cur = 0;
#pragma unroll
    for (int d = 1; d < 256; d <<= 1) {
        int x = sbuf[cur][t];
        if (t >= d) x += sbuf[cur][t - d];
        sbuf[1 - cur][t] = x;
        cur ^= 1;
        __syncthreads();
    }
    if (t < NUM_SCAN_BLOCKS) pre[t] = sbuf[cur][t] - val;
    __syncthreads();

    int idx = blockIdx.x * blockDim.x + t;
    if (idx < N_NODES) {
        int cnt = g_cnt[idx];
        int off = g_off[idx] + pre[idx / NODES_PER_SCAN_BLK];
        g_off[idx] = off;
        g_cur[idx] = off;
        g_dinv[idx] = rsqrtf((float)(cnt + 1));  // +1 self-loop
        g_cnt[idx] = 0;                          // self-clean for next launch
    }
}

// scatter srcs into dest-keyed CSR buckets
__global__ __launch_bounds__(256) void k_fill(const void* __restrict__ ei, int E) {
    int is64 = detect_is64((const unsigned int*)ei);
    int e = (blockIdx.x * blockDim.x + threadIdx.x) * 2;
    if (e + 1 < E) {
        int c0, c1, s0, s1;
        load_idx2(ei, (size_t)E + e, is64, c0, c1);
        load_idx2(ei, (size_t)e, is64, s0, s1);
        if ((unsigned)c0 < (unsigned)N_NODES && (unsigned)s0 < (unsigned)N_NODES) {
            int p = atomicAdd(&g_cur[c0], 1);
            g_src[p] = s0;
        }
        if ((unsigned)c1 < (unsigned)N_NODES && (unsigned)s1 < (unsigned)N_NODES) {
            int p = atomicAdd(&g_cur[c1], 1);
            g_src[p] = s1;
        }
    } else if (e < E) {
        int c = load_idx(ei, (size_t)E + e, is64);
        int s = load_idx(ei, (size_t)e, is64);
        if ((unsigned)c < (unsigned)N_NODES && (unsigned)s < (unsigned)N_NODES) {
            int p = atomicAdd(&g_cur[c], 1);
            g_src[p] = s;
        }
    }
}

// ------------------------------------------------------------------
// one block: Wc = W1 @ W2 -> g_Wch (fp16, transposed [n][k]); bv = b1 @ W2
__global__ __launch_bounds__(256) void k_wc(
    const float* __restrict__ W1, const float* __restrict__ W2,
    const float* __restrict__ b1)
{
    __shared__ float w1s[64 * 64];
    __shared__ float w2s[64 * 64];
    int t = threadIdx.x;
    for (int i = t; i < 1024; i += 256) {
        ((float4*)w1s)[i] = ((const float4*)W1)[i];
        ((float4*)w2s)[i] = ((const float4*)W2)[i];
    }
    __syncthreads();
    int row = t >> 2;            // k index of Wc
    int cb  = (t & 3) * 16;      // n base
    float acc[16];
#pragma unroll
    for (int j = 0; j < 16; ++j) acc[j] = 0.f;
    for (int k = 0; k < 64; ++k) {
        float a = w1s[row * 64 + k];
#pragma unroll
        for (int j = 0; j < 16; ++j)
            acc[j] = fmaf(a, w2s[k * 64 + cb + j], acc[j]);
    }
#pragma unroll
    for (int j = 0; j < 16; ++j)
        g_Wch[(cb + j) * 64 + row] = __float2half(acc[j]);   // [n][k]
    if (t < 64) {
        float s = 0.f;
        for (int k = 0; k < 64; ++k) s = fmaf(b1[k], w2s[k * 64 + t], s);
        g_bv[t] = s;
    }
}

// ------------------------------------------------------------------
// HMMA GEMM: zs[r,:] = dinv[r] * (x[r,:] @ Wc)  -> fp16 g_zh
// 128 rows/block, 8 warps: each warp m16 x n64 via mma.m16n8k16, fp32 accum.
__global__ __launch_bounds__(256) void k_gemm(
    const float* __restrict__ xa, const float* __restrict__ xb)
{
    __shared__ __align__(16) __half As[128][72];   // A tile / output staging
    __shared__ __align__(16) __half Bs[64][72];    // Wc^T [n][k]
    int tid = threadIdx.x;
    int warp = tid >> 5, lane = tid & 31;
    int block_row = blockIdx.x * GEMM_ROWS;

    // stage B (4096 halves): 4 threads/row, 2 uint4 each
    {
        int r = tid >> 2, seg = tid & 3;
        const uint4* src = (const uint4*)(g_Wch + r * 64 + seg * 16);
        *(uint4*)(&Bs[r][seg * 16])     = src[0];
        *(uint4*)(&Bs[r][seg * 16 + 8]) = src[1];
    }
    // stage A: 128 rows x 64 fp32 -> fp16 (clamped tail rows; stores guarded)
#pragma unroll
    for (int p = 0; p < 8; ++p) {
        int r = p * 16 + (tid >> 4);
        int c = (tid & 15) * 4;
        int gr = block_row + r;
        int cr = (gr < N_NODES) ? gr : (N_NODES - 1);
        const float* xrow = (cr < N_USERS)
            ? (xa + (size_t)cr * DIM)
            : (xb + (size_t)(cr - N_USERS) * DIM);
        float4 v = *(const float4*)(xrow + c);
        *(__half2*)(&As[r][c])     = __floats2half2_rn(v.x, v.y);
        *(__half2*)(&As[r][c + 2]) = __floats2half2_rn(v.z, v.w);
    }
    __syncthreads();

    int g = lane >> 2, tig = lane & 3;
    float acc[8][4];
#pragma unroll
    for (int n = 0; n < 8; ++n)
#pragma unroll
        for (int j = 0; j < 4; ++j) acc[n][j] = 0.f;

#pragma unroll
    for (int kc = 0; kc < 4; ++kc) {
        unsigned a0 = *(unsigned*)(&As[warp * 16 + g][kc * 16 + tig * 2]);
        unsigned a1 = *(unsigned*)(&As[warp * 16 + g + 8][kc * 16 + tig * 2]);
        unsigned a2 = *(unsigned*)(&As[warp * 16 + g][kc * 16 + tig * 2 + 8]);
        unsigned a3 = *(unsigned*)(&As[warp * 16 + g + 8][kc * 16 + tig * 2 + 8]);
#pragma unroll
        for (int n = 0; n < 8; ++n) {
            unsigned b0 = *(unsigned*)(&Bs[n * 8 + g][kc * 16 + tig * 2]);
            unsigned b1 = *(unsigned*)(&Bs[n * 8 + g][kc * 16 + tig * 2 + 8]);
            asm volatile(
                "mma.sync.aligned.m16n8k16.row.col.f32.f16.f16.f32 "
                "{%0,%1,%2,%3}, {%4,%5,%6,%7}, {%8,%9}, {%0,%1,%2,%3};"
                : "+f"(acc[n][0]), "+f"(acc[n][1]), "+f"(acc[n][2]), "+f"(acc[n][3])
                : "r"(a0), "r"(a1), "r"(a2), "r"(a3), "r"(b0), "r"(b1));
        }
    }
    __syncthreads();   // done reading As; reuse as output staging

    int r0 = warp * 16 + g, r1 = r0 + 8;
    int gr0 = block_row + r0, gr1 = block_row + r1;
    float d0 = g_dinv[(gr0 < N_NODES) ? gr0 : (N_NODES - 1)];
    float d1 = g_dinv[(gr1 < N_NODES) ? gr1 : (N_NODES - 1)];
#pragma unroll
    for (int n = 0; n < 8; ++n) {
        *(__half2*)(&As[r0][n * 8 + tig * 2]) =
            __floats2half2_rn(acc[n][0] * d0, acc[n][1] * d0);
        *(__half2*)(&As[r1][n * 8 + tig * 2]) =
            __floats2half2_rn(acc[n][2] * d1, acc[n][3] * d1);
    }
    __syncthreads();
    // coalesced fp16 store: 128 rows x 8 uint4 segments
#pragma unroll
    for (int p = 0; p < 4; ++p) {
        int idx = p * 256 + tid;
        int r = idx >> 3, seg = idx & 7;
        int gr = block_row + r;
        if (gr < N_NODES)
            *(uint4*)(g_zh + (size_t)gr * DIM + seg * 8) = *(uint4*)(&As[r][seg * 8]);
    }
}

// ------------------------------------------------------------------
// hop 1: u1[c,:] = dinv^2[c] * (zs[c,:] + sum zs[src,:])   (g_zh -> g_hh)
//        lane0 accumulates sum dinv[src] -> a[c] = dinv[c]*(dinv[c]+sum)
__global__ __launch_bounds__(256) void k_agg1()
{
    int t = blockIdx.x * blockDim.x + threadIdx.x;
    int node = t >> 3;
    if (node >= N_NODES) return;
    int lane = (t & 7) * 8;
    bool lead = (t & 7) == 0;

    float acc[8] = {0.f, 0.f, 0.f, 0.f, 0.f, 0.f, 0.f, 0.f};
    float asum = 0.f;
    h8_add(acc, *(const uint4*)(g_zh + (size_t)node * DIM + lane));  // self
    int s0 = g_off[node];
    int cnt = g_cur[node] - s0;
    for (int i = 0; i < cnt; ++i) {
        int src = g_src[s0 + i];
        h8_add(acc, *(const uint4*)(g_zh + (size_t)src * DIM + lane));
        if (lead) asum += g_dinv[src];
    }
    float dn = g_dinv[node];
    float d2 = dn * dn;
    __half2 h0 = __floats2half2_rn(d2 * acc[0], d2 * acc[1]);
    __half2 h1 = __floats2half2_rn(d2 * acc[2], d2 * acc[3]);
    __half2 h2 = __floats2half2_rn(d2 * acc[4], d2 * acc[5]);
    __half2 h3 = __floats2half2_rn(d2 * acc[6], d2 * acc[7]);
    uint4 val;
    val.x = *(unsigned int*)&h0; val.y = *(unsigned int*)&h1;
    val.z = *(unsigned int*)&h2; val.w = *(unsigned int*)&h3;
    *(uint4*)(g_hh + (size_t)node * DIM + lane) = val;
    if (lead) g_a[node] = dn * (dn + asum);
}

// hop 2 + epilogue: out[c,:] = dinv[c]*(u1[c,:] + sum u1[src,:]) + a[c]*bv + b2
__global__ __launch_bounds__(256) void k_agg2(
    const float* __restrict__ b2, float* __restrict__ out)
{
    int t = blockIdx.x * blockDim.x + threadIdx.x;
    int node = t >> 3;
    if (node >= N_NODES) return;
    int lane = (t & 7) * 8;

    float acc[8] = {0.f, 0.f, 0.f, 0.f, 0.f, 0.f, 0.f, 0.f};
    h8_add(acc, *(const uint4*)(g_hh + (size_t)node * DIM + lane));  // self
    int s0 = g_off[node];
    int cnt = g_cur[node] - s0;
    for (int i = 0; i < cnt; ++i) {
        int src = g_src[s0 + i];
        h8_add(acc, *(const uint4*)(g_hh + (size_t)src * DIM + lane));
    }
    float dn = g_dinv[node];
    float av = g_a[node];
    float4 bv0 = *(const float4*)(g_bv + lane);
    float4 bv1 = *(const float4*)(g_bv + lane + 4);
    float4 b20 = *(const float4*)(b2 + lane);
    float4 b21 = *(const float4*)(b2 + lane + 4);
    float* dst = out + (size_t)node * DIM + lane;
    float4 o0 = make_float4(
        fmaf(dn, acc[0], fmaf(av, bv0.x, b20.x)),
        fmaf(dn, acc[1], fmaf(av, bv0.y, b20.y)),
        fmaf(dn, acc[2], fmaf(av, bv0.z, b20.z)),
        fmaf(dn, acc[3], fmaf(av, bv0.w, b20.w)));
    float4 o1 = make_float4(
        fmaf(dn, acc[4], fmaf(av, bv1.x, b21.x)),
        fmaf(dn, acc[5], fmaf(av, bv1.y, b21.y)),
        fmaf(dn, acc[6], fmaf(av, bv1.z, b21.z)),
        fmaf(dn, acc[7], fmaf(av, bv1.w, b21.w)));
    *(float4*)dst       = o0;
    *(float4*)(dst + 4) = o1;
}

// ------------------------------------------------------------------
extern "C" void kernel_launch(void* const* d_in, const int* in_sizes, int n_in,
                              void* d_out, int out_size)
{
    const void*  ei   = d_in[0];
    const float* user = (const float*)d_in[1];
    const float* item = (const float*)d_in[2];
    const float* W1   = (const float*)d_in[3];
    const float* b1   = (const float*)d_in[4];
    const float* W2   = (const float*)d_in[5];
    const float* b2   = (const float*)d_in[6];
    float* out        = (float*)d_out;
    int E = in_sizes[0] / 2;

    int zb  = (N_NODES + 255) / 256;
    int eb2 = (E / 2 + 255) / 256;
    int agg_blocks  = (N_NODES * 8 + 255) / 256;        // 6250
    int gemm_blocks = (N_NODES + GEMM_ROWS - 1) / GEMM_ROWS;  // 1563

    // one-time infra (created on the first, non-captured, correctness call)
    static cudaStream_t s_aux = nullptr;
    static cudaEvent_t ev_fork = nullptr, ev_wc = nullptr, ev_fill = nullptr,
                       ev_scan = nullptr;
    if (s_aux == nullptr) {
        cudaStreamCreateWithFlags(&s_aux, cudaStreamNonBlocking);
        cudaEventCreateWithFlags(&ev_fork, cudaEventDisableTiming);
        cudaEventCreateWithFlags(&ev_wc,   cudaEventDisableTiming);
        cudaEventCreateWithFlags(&ev_fill, cudaEventDisableTiming);
        cudaEventCreateWithFlags(&ev_scan, cudaEventDisableTiming);
    }

    // fork: aux stream computes Wc (independent of graph prep)
    cudaEventRecord(ev_fork, 0);
    cudaStreamWaitEvent(s_aux, ev_fork, 0);
    k_wc<<<1, 256, 0, s_aux>>>(W1, W2, b1);
    cudaEventRecord(ev_wc, s_aux);

    // main stream: graph prep chain (g_cnt arrives zeroed — self-cleaning)
    k_hist<<<eb2, 256>>>(ei, E);
    k_scan1<<<NUM_SCAN_BLOCKS, 256>>>();
    k_scan3<<<zb, 256>>>();

    // fork: fill (L2/atomic-bound) concurrent with gemm (tensor/mem-bound)
    cudaEventRecord(ev_scan, 0);
    cudaStreamWaitEvent(s_aux, ev_scan, 0);
    k_fill<<<eb2, 256, 0, s_aux>>>(ei, E);
    cudaEventRecord(ev_fill, s_aux);

    cudaStreamWaitEvent(0, ev_wc, 0);          // gemm needs Wch + dinv
    k_gemm<<<gemm_blocks, 256>>>(user, item);  // zs (fp16) -> g_zh

    // join: aggregation needs both gemm (main) and fill (aux)
    cudaStreamWaitEvent(0, ev_fill, 0);
    k_agg1<<<agg_blocks, 256>>>();             // u1 (fp16), a
    k_agg2<<<agg_blocks, 256>>>(b2, out);      // out = A u1 + a*bv + b2
}